// round 5
// baseline (speedup 1.0000x reference)
#include <cuda_runtime.h>
#include <stdint.h>

#define BB    32
#define NBOX  8192
#define MGT   256
#define NP    8448        // NBOX + MGT
#define NSAMP 512
#define NFG   128
#define NBIN  2048
#define CAP   512

// scratch (device globals -- no allocation allowed)
__device__ unsigned long long g_keys[BB * NP];
__device__ unsigned int       g_meta[BB * NP];

__device__ __forceinline__ uint32_t rotl32(uint32_t x, int d) {
    return (x << d) | (x >> (32 - d));
}

// JAX *partitionable* threefry, key = (0, 42). bits(p) = x0 ^ x1 of
// threefry2x32((0,42), (0, p))
__device__ __forceinline__ uint32_t threefry_bits(uint32_t p) {
    const uint32_t ks0 = 0u, ks1 = 42u, ks2 = 0x1BD11BF0u;  // 0x1BD11BDA ^ 0 ^ 42
    uint32_t x0 = 0u + ks0;
    uint32_t x1 = p + ks1;
#define TF_R(r) { x0 += x1; x1 = rotl32(x1, (r)); x1 ^= x0; }
    TF_R(13) TF_R(15) TF_R(26) TF_R(6)   x0 += ks1; x1 += ks2 + 1u;
    TF_R(17) TF_R(29) TF_R(16) TF_R(24)  x0 += ks2; x1 += ks0 + 2u;
    TF_R(13) TF_R(15) TF_R(26) TF_R(6)   x0 += ks0; x1 += ks1 + 3u;
    TF_R(17) TF_R(29) TF_R(16) TF_R(24)  x0 += ks1; x1 += ks2 + 4u;
    TF_R(13) TF_R(15) TF_R(26) TF_R(6)   x0 += ks2; x1 += ks0 + 5u;
#undef TF_R
    return x0 ^ x1;
}

// ---------------------------------------------------------------------------
// Kernel 1: per-box max-IoU matching (valid-gt prefix only) + threefry key.
// ---------------------------------------------------------------------------
__global__ __launch_bounds__(256)
void roi_match_kernel(const float* __restrict__ boxes,
                      const float* __restrict__ gt_boxes) {
    __shared__ float4 sg[MGT];
    __shared__ float  sga[MGT];

    const int b = blockIdx.y;
    int nv;
    {
        const int j = threadIdx.x;               // 256 threads == MGT
        float4 g = ((const float4*)gt_boxes)[b * MGT + j];
        float mx = fmaxf(fmaxf(g.x, g.y), fmaxf(g.z, g.w));
        bool valid = (mx >= 0.0f);
        float area = (g.z - g.x) * (g.w - g.y);
        sg[j] = g; sga[j] = area;
        nv = __syncthreads_count(valid);         // valid gts are a prefix
    }

    const int i = blockIdx.x * 256 + threadIdx.x;   // grid exact: i < NP
    float4 bx = (i < NBOX) ? ((const float4*)boxes)[b * NBOX + i]
                           : ((const float4*)gt_boxes)[b * MGT + (i - NBOX)];
    const float ab = (bx.z - bx.x) * (bx.w - bx.y);

    // branchless running-argmax of iou = inter/uni via cross-multiplication.
    // bi/bu starts at 0/1 (iou 0), mi=0 -> matches ref argmax-of-zeros.
    float bi = 0.0f, bu = 1.0f;
    int mi = 0;
#pragma unroll 4
    for (int g = 0; g < nv; ++g) {
        float4 gb = sg[g];
        float dy = fminf(bx.z, gb.z) - fmaxf(bx.x, gb.x);
        float dx = fminf(bx.w, gb.w) - fmaxf(bx.y, gb.y);
        float inter = fmaxf(dy, 0.0f) * fmaxf(dx, 0.0f);
        float uni   = (ab + sga[g]) - inter;
        // inter/uni > bi/bu  <=>  inter*bu > bi*uni  (uni, bu > 0)
        bool upd = (inter * bu > bi * uni);
        bi = upd ? inter : bi;
        bu = upd ? uni   : bu;
        mi = upd ? g     : mi;
    }
    bool pos = (bi > 0.0f) && (__fdiv_rn(bi, bu) >= 0.5f);

    uint32_t p = (uint32_t)(b * NP + i);
    uint32_t m = threefry_bits(p) >> 9;       // 23-bit mantissa; order(r)==order(m)
    g_keys[b * NP + i] = ((unsigned long long)(pos ? 1u : 0u) << 40)
        | (((unsigned long long)(0x7FFFFFu - m)) << 14) | (unsigned)i;
    g_meta[b * NP + i] = (unsigned)mi | (pos ? (1u << 16) : 0u);
}

// ---------------------------------------------------------------------------
// Kernel 2: per-image histogram radix-select + hybrid 512-sort + gather.
// ---------------------------------------------------------------------------
__device__ __forceinline__ void write_record(
    const float* __restrict__ boxes, const float* __restrict__ gt_boxes,
    const int* __restrict__ gt_classes, float* __restrict__ out,
    int b, unsigned i, unsigned slot)
{
    float4 roi = (i < NBOX)
        ? ((const float4*)boxes)[b * NBOX + i]
        : ((const float4*)gt_boxes)[b * MGT + (i - NBOX)];
    unsigned mt = g_meta[b * NP + i];
    bool pos = (mt >> 16) & 1u;
    int  mi  = (int)(mt & 0xFFFFu);
    float4 gb = make_float4(0.f, 0.f, 0.f, 0.f);
    float cls = 0.0f, gidx = -1.0f;
    if (pos) {
        gb   = ((const float4*)gt_boxes)[b * MGT + mi];
        cls  = (float)gt_classes[b * MGT + mi];
        gidx = (float)mi;
    }
    size_t base = (size_t)(b * NSAMP + slot);
    float* o1 = out + base * 4;                                   // rois
    o1[0] = roi.x; o1[1] = roi.y; o1[2] = roi.z; o1[3] = roi.w;
    float* o2 = out + (size_t)BB * NSAMP * 4 + base * 4;          // matched gt boxes
    o2[0] = gb.x; o2[1] = gb.y; o2[2] = gb.z; o2[3] = gb.w;
    out[(size_t)2 * BB * NSAMP * 4 + base] = cls;                 // classes
    out[(size_t)2 * BB * NSAMP * 4 + (size_t)BB * NSAMP + base] = gidx; // indices
}

__global__ __launch_bounds__(1024)
void roi_sample_kernel(const float* __restrict__ boxes,
                       const float* __restrict__ gt_boxes,
                       const int*   __restrict__ gt_classes,
                       float* __restrict__ out) {
    extern __shared__ unsigned char smem_raw[];
    unsigned long long* keys = (unsigned long long*)smem_raw;    // NP
    unsigned long long* LP   = keys + NP;                        // CAP
    unsigned long long* LN   = LP + CAP;                         // CAP
    unsigned long long* selk = LN + CAP;                         // NSAMP
    unsigned int*       hP   = (unsigned int*)(selk + NSAMP);    // NBIN
    unsigned int*       hN   = hP + NBIN;                        // NBIN

    __shared__ unsigned wsP[32], wsN[32];
    __shared__ unsigned sh_bp, sh_bn, sh_befP, sh_befN;
    __shared__ unsigned cntP, cntN, cntS;
    __shared__ unsigned long long sh_KP, sh_KN;

    const int b = blockIdx.x;
    const int t = threadIdx.x;
    const int T = 1024;
    const int lane = t & 31, wid = t >> 5;

    if (t == 0) { cntP = 0; cntN = 0; cntS = 0; sh_KP = ~0ull; sh_KN = ~0ull; }
    for (int k = t; k < NBIN; k += T) { hP[k] = 0u; hN[k] = 0u; }
    __syncthreads();

    // load keys + histogram on bits 36..26 (top 11 bits of inv-mantissa)
    for (int p = t; p < NP; p += T) {
        unsigned long long w = g_keys[b * NP + p];
        keys[p] = w;
        unsigned bin = (unsigned)(w >> 26) & 0x7FFu;
        if (w >> 40) atomicAdd(&hP[bin], 1u);
        else         atomicAdd(&hN[bin], 1u);
    }
    __syncthreads();

    // hierarchical inclusive scan: thread owns bins 2t, 2t+1
    unsigned a0P = hP[2 * t], a1P = hP[2 * t + 1], sP = a0P + a1P;
    unsigned a0N = hN[2 * t], a1N = hN[2 * t + 1], sN = a0N + a1N;
#pragma unroll
    for (int off = 1; off < 32; off <<= 1) {
        unsigned vP = __shfl_up_sync(0xFFFFFFFFu, sP, off);
        unsigned vN = __shfl_up_sync(0xFFFFFFFFu, sN, off);
        if (lane >= off) { sP += vP; sN += vN; }
    }
    if (lane == 31) { wsP[wid] = sP; wsN[wid] = sN; }
    __syncthreads();
    if (wid == 0) {
        unsigned xP = wsP[lane], xN = wsN[lane];
#pragma unroll
        for (int off = 1; off < 32; off <<= 1) {
            unsigned vP = __shfl_up_sync(0xFFFFFFFFu, xP, off);
            unsigned vN = __shfl_up_sync(0xFFFFFFFFu, xN, off);
            if (lane >= off) { xP += vP; xN += vN; }
        }
        wsP[lane] = xP; wsN[lane] = xN;   // inclusive warp totals
    }
    __syncthreads();

    const unsigned total_pos = wsP[31];
    const unsigned n_pos = (total_pos < (unsigned)NFG) ? total_pos : (unsigned)NFG;
    const unsigned quota = (unsigned)NSAMP - n_pos;
    const bool needPsel = (total_pos > (unsigned)NFG);

    // boundary bins straight from registers (no hist writeback)
    {
        unsigned baseP = wid ? wsP[wid - 1] : 0u;
        unsigned baseN = wid ? wsN[wid - 1] : 0u;
        unsigned incl1P = baseP + sP, incl0P = incl1P - a1P, prevP = incl0P - a0P;
        unsigned incl1N = baseN + sN, incl0N = incl1N - a1N, prevN = incl0N - a0N;
        if (needPsel) {
            if (incl0P >= (unsigned)NFG && prevP  < (unsigned)NFG) { sh_bp = 2u*t;   sh_befP = prevP; }
            if (incl1P >= (unsigned)NFG && incl0P < (unsigned)NFG) { sh_bp = 2u*t+1; sh_befP = incl0P; }
        }
        if (incl0N >= quota && prevN  < quota) { sh_bn = 2u*t;   sh_befN = prevN; }
        if (incl1N >= quota && incl0N < quota) { sh_bn = 2u*t+1; sh_befN = incl0N; }
    }
    __syncthreads();

    // collect boundary-bin items (expected ~4 each)
    {
        unsigned bp = needPsel ? sh_bp : 0xFFFFFFFFu;
        unsigned bn = sh_bn;
        for (int p = t; p < NP; p += T) {
            unsigned long long w = keys[p];
            unsigned bin = (unsigned)(w >> 26) & 0x7FFu;
            if (w >> 40) {
                if (bin == bp) { unsigned j = atomicAdd(&cntP, 1u); if (j < CAP) LP[j] = w; }
            } else {
                if (bin == bn) { unsigned j = atomicAdd(&cntN, 1u); if (j < CAP) LN[j] = w; }
            }
        }
    }
    if (t < NSAMP) selk[t] = ~0ull;
    __syncthreads();

    // exact rank within boundary bins -> cutoff keys (keys are unique)
    {
        unsigned cp = cntP < CAP ? cntP : CAP;
        unsigned cn = cntN < CAP ? cntN : CAP;
        if (needPsel && (unsigned)t < cp) {
            unsigned long long k = LP[t]; unsigned r = 0;
            for (unsigned l = 0; l < cp; ++l) r += (LP[l] < k);
            if (r == ((unsigned)NFG - sh_befP) - 1u) sh_KP = k;
        }
        if ((unsigned)t < cn) {
            unsigned long long k = LN[t]; unsigned r = 0;
            for (unsigned l = 0; l < cn; ++l) r += (LN[l] < k);
            if (r == (quota - sh_befN) - 1u) sh_KN = k;
        }
    }
    __syncthreads();

    // final selection: exactly 512; re-key by RNE-rounded score mantissa.
    // score = 2.0f + r rounds r's 23-bit mantissa m to 2^-22 grid:
    //   h = (m>>1) + ((m&1) & ((m>>1)&1)); ties broken by idx asc.
    {
        unsigned long long KP = sh_KP, KN = sh_KN;
        for (int p = t; p < NP; p += T) {
            unsigned long long w = keys[p];
            bool sel = (w >> 40) ? (w <= KP) : (w <= KN);
            if (sel) {
                unsigned i  = (unsigned)(w & 0x3FFFu);
                unsigned mm = 0x7FFFFFu - (unsigned)((w >> 14) & 0x7FFFFFu);
                unsigned h  = (mm >> 1) + ((mm & 1u) & ((mm >> 1) & 1u));
                unsigned j  = atomicAdd(&cntS, 1u);
                selk[j] = (((unsigned long long)(0x7FFFFFu - h)) << 14) | i;
            }
        }
    }
    __syncthreads();

    // hybrid bitonic sort of 512 keys: shuffle for j<32, smem for j>=32
    unsigned long long v = (t < NSAMP) ? selk[t] : ~0ull;
    for (unsigned k = 2; k <= (unsigned)NSAMP; k <<= 1) {
        for (unsigned j = k >> 1; j > 0; j >>= 1) {
            bool dir   = ((t & k) == 0);
            bool lower = ((t & j) == 0);
            bool keepmin = (dir == lower);
            if (j >= 32) {
                if (t < NSAMP) selk[t] = v;
                __syncthreads();
                if (t < NSAMP) {
                    unsigned long long u = selk[t ^ j];
                    v = keepmin ? (v < u ? v : u) : (v > u ? v : u);
                }
                __syncthreads();
            } else {
                unsigned long long u = __shfl_xor_sync(0xFFFFFFFFu, v, j);
                if (t < NSAMP)
                    v = keepmin ? (v < u ? v : u) : (v > u ? v : u);
            }
        }
    }

    // gather outputs (value still in register)
    if (t < NSAMP) {
        unsigned i = (unsigned)(v & 0x3FFFu);
        write_record(boxes, gt_boxes, gt_classes, out, b, i, (unsigned)t);
    }
}

extern "C" void kernel_launch(void* const* d_in, const int* in_sizes, int n_in,
                              void* d_out, int out_size) {
    (void)out_size;
    const float* boxes      = (const float*)d_in[0];
    const float* gt_boxes   = (const float*)d_in[1];
    const int*   gt_classes = (const int*)d_in[2];
    for (int k = 0; k < n_in; ++k) {
        if (in_sizes[k] == BB * NBOX * 4) boxes      = (const float*)d_in[k];
        else if (in_sizes[k] == BB * MGT * 4) gt_boxes = (const float*)d_in[k];
        else if (in_sizes[k] == BB * MGT)     gt_classes = (const int*)d_in[k];
    }
    float* out = (float*)d_out;

    dim3 g1(NP / 256, BB);
    roi_match_kernel<<<g1, 256>>>(boxes, gt_boxes);

    size_t smem = (size_t)NP * 8 + 2 * (size_t)CAP * 8 + (size_t)NSAMP * 8
                + 2 * (size_t)NBIN * 4;   // 96256 B
    cudaFuncSetAttribute(roi_sample_kernel,
                         cudaFuncAttributeMaxDynamicSharedMemorySize, (int)smem);
    roi_sample_kernel<<<BB, 1024, smem>>>(boxes, gt_boxes, gt_classes, out);
}

// round 6
// speedup vs baseline: 1.3973x; 1.3973x over previous
#include <cuda_runtime.h>
#include <stdint.h>

#define BB    32
#define NBOX  8192
#define MGT   256
#define NP    8448        // NBOX + MGT
#define NSAMP 512
#define NFG   128
#define NBIN  2048
#define CAP   512

// scratch (device globals -- no allocation allowed)
__device__ unsigned long long g_keys[BB * NP];
__device__ unsigned int       g_meta[BB * NP];

__device__ __forceinline__ uint32_t rotl32(uint32_t x, int d) {
    return (x << d) | (x >> (32 - d));
}

// JAX *partitionable* threefry, key = (0, 42). bits(p) = x0 ^ x1 of
// threefry2x32((0,42), (0, p))
__device__ __forceinline__ uint32_t threefry_bits(uint32_t p) {
    const uint32_t ks0 = 0u, ks1 = 42u, ks2 = 0x1BD11BF0u;  // 0x1BD11BDA ^ 0 ^ 42
    uint32_t x0 = 0u + ks0;
    uint32_t x1 = p + ks1;
#define TF_R(r) { x0 += x1; x1 = rotl32(x1, (r)); x1 ^= x0; }
    TF_R(13) TF_R(15) TF_R(26) TF_R(6)   x0 += ks1; x1 += ks2 + 1u;
    TF_R(17) TF_R(29) TF_R(16) TF_R(24)  x0 += ks2; x1 += ks0 + 2u;
    TF_R(13) TF_R(15) TF_R(26) TF_R(6)   x0 += ks0; x1 += ks1 + 3u;
    TF_R(17) TF_R(29) TF_R(16) TF_R(24)  x0 += ks1; x1 += ks2 + 4u;
    TF_R(13) TF_R(15) TF_R(26) TF_R(6)   x0 += ks2; x1 += ks0 + 5u;
#undef TF_R
    return x0 ^ x1;
}

// ---------------------------------------------------------------------------
// Kernel 1: max-IoU matching, 2 boxes/thread, valid-gt prefix, if-guarded
// update (branch mostly coherently untaken -> skips the dependency chain).
// grid (17, 32): blocks 0..15 handle 512 proposals each; block 16 the 256 gts.
// ---------------------------------------------------------------------------
__global__ __launch_bounds__(256)
void roi_match_kernel(const float* __restrict__ boxes,
                      const float* __restrict__ gt_boxes) {
    __shared__ float4 sg[MGT];
    __shared__ float  sga[MGT];

    const int b = blockIdx.y;
    const int t = threadIdx.x;
    int nv;
    {
        float4 g = ((const float4*)gt_boxes)[b * MGT + t];
        float mx = fmaxf(fmaxf(g.x, g.y), fmaxf(g.z, g.w));
        bool valid = (mx >= 0.0f);
        sg[t] = g;
        sga[t] = (g.z - g.x) * (g.w - g.y);
        nv = __syncthreads_count(valid);         // valid gts are a prefix
    }

    const bool two = (blockIdx.x < 16);
    const int i0 = two ? (blockIdx.x * 512 + t) : (NBOX + t);
    const int i1 = i0 + 256;

    float4 A = (i0 < NBOX) ? ((const float4*)boxes)[b * NBOX + i0]
                           : ((const float4*)gt_boxes)[b * MGT + (i0 - NBOX)];
    float4 Bx = two ? ((const float4*)boxes)[b * NBOX + i1] : A;

    const float abA = (A.z - A.x) * (A.w - A.y);
    const float abB = (Bx.z - Bx.x) * (Bx.w - Bx.y);

    // running argmax of iou = inter/uni via cross-multiplication.
    // bi=-1 sentinel: first overlapping gt always wins; bi>0 <=> some overlap.
    float biA = -1.0f, buA = 1.0f; int miA = 0;
    float biB = -1.0f, buB = 1.0f; int miB = 0;
#pragma unroll 4
    for (int g = 0; g < nv; ++g) {
        float4 gb = sg[g];
        float ga  = sga[g];
        {
            float dy = fminf(A.z, gb.z) - fmaxf(A.x, gb.x);
            float dx = fminf(A.w, gb.w) - fmaxf(A.y, gb.y);
            if (dy > 0.0f && dx > 0.0f) {
                float inter = dy * dx;
                float uni   = (abA + ga) - inter;
                if (inter * buA > biA * uni) { biA = inter; buA = uni; miA = g; }
            }
        }
        {
            float dy = fminf(Bx.z, gb.z) - fmaxf(Bx.x, gb.x);
            float dx = fminf(Bx.w, gb.w) - fmaxf(Bx.y, gb.y);
            if (dy > 0.0f && dx > 0.0f) {
                float inter = dy * dx;
                float uni   = (abB + ga) - inter;
                if (inter * buB > biB * uni) { biB = inter; buB = uni; miB = g; }
            }
        }
    }
    bool posA = (biA > 0.0f) && (__fdiv_rn(biA, buA) >= 0.5f);
    bool posB = (biB > 0.0f) && (__fdiv_rn(biB, buB) >= 0.5f);

    {
        uint32_t p = (uint32_t)(b * NP + i0);
        uint32_t m = threefry_bits(p) >> 9;   // 23-bit mantissa; order(r)==order(m)
        g_keys[b * NP + i0] =
            (((unsigned long long)(0x7FFFFFu - m)) << 14) | (unsigned)i0;
        g_meta[b * NP + i0] = (unsigned)miA | (posA ? (1u << 16) : 0u);
    }
    if (two) {
        uint32_t p = (uint32_t)(b * NP + i1);
        uint32_t m = threefry_bits(p) >> 9;
        g_keys[b * NP + i1] =
            (((unsigned long long)(0x7FFFFFu - m)) << 14) | (unsigned)i1;
        g_meta[b * NP + i1] = (unsigned)miB | (posB ? (1u << 16) : 0u);
    }
}

// ---------------------------------------------------------------------------
// Kernel 2: per-image histogram radix-select + 512-sort + gather.
// (round-4 version, verbatim — known 21.5us)
// ---------------------------------------------------------------------------
__device__ __forceinline__ void write_record(
    const float* __restrict__ boxes, const float* __restrict__ gt_boxes,
    const int* __restrict__ gt_classes, const unsigned int* meta,
    float* __restrict__ out, int b, unsigned i, unsigned slot)
{
    float4 roi = (i < NBOX)
        ? ((const float4*)boxes)[b * NBOX + i]
        : ((const float4*)gt_boxes)[b * MGT + (i - NBOX)];
    unsigned mt = meta[i];
    bool pos = (mt >> 16) & 1u;
    int  mi  = (int)(mt & 0xFFFFu);
    float4 gb = make_float4(0.f, 0.f, 0.f, 0.f);
    float cls = 0.0f, gidx = -1.0f;
    if (pos) {
        gb   = ((const float4*)gt_boxes)[b * MGT + mi];
        cls  = (float)gt_classes[b * MGT + mi];
        gidx = (float)mi;
    }
    size_t base = (size_t)(b * NSAMP + slot);
    float* o1 = out + base * 4;                                   // rois
    o1[0] = roi.x; o1[1] = roi.y; o1[2] = roi.z; o1[3] = roi.w;
    float* o2 = out + (size_t)BB * NSAMP * 4 + base * 4;          // matched gt boxes
    o2[0] = gb.x; o2[1] = gb.y; o2[2] = gb.z; o2[3] = gb.w;
    out[(size_t)2 * BB * NSAMP * 4 + base] = cls;                 // classes
    out[(size_t)2 * BB * NSAMP * 4 + (size_t)BB * NSAMP + base] = gidx; // indices
}

__global__ __launch_bounds__(1024)
void roi_sample_kernel(const float* __restrict__ boxes,
                       const float* __restrict__ gt_boxes,
                       const int*   __restrict__ gt_classes,
                       float* __restrict__ out) {
    extern __shared__ unsigned char smem_raw[];
    unsigned long long* keys = (unsigned long long*)smem_raw;    // NP
    unsigned long long* LP   = keys + NP;                        // CAP
    unsigned long long* LN   = LP + CAP;                         // CAP
    unsigned long long* selk = LN + CAP;                         // NSAMP
    unsigned int*       meta = (unsigned int*)(selk + NSAMP);    // NP
    unsigned int*       hP   = meta + NP;                        // NBIN
    unsigned int*       hN   = hP + NBIN;                        // NBIN

    __shared__ unsigned sh_bp, sh_bn, sh_befP, sh_befN;
    __shared__ unsigned cntP, cntN, cntS;
    __shared__ unsigned long long sh_KP, sh_KN;

    const int b = blockIdx.x;
    const int t = threadIdx.x;
    const int T = 1024;

    if (t == 0) {
        cntP = 0; cntN = 0; cntS = 0;
        sh_KP = ~0ull; sh_KN = ~0ull;
    }
    for (int k = t; k < NBIN; k += T) { hP[k] = 0u; hN[k] = 0u; }

    // load keys + meta, build histograms on top-11 key bits (bits 36..26)
    for (int p = t; p < NP; p += T) {
        unsigned long long w = g_keys[b * NP + p];
        unsigned mt = g_meta[b * NP + p];
        keys[p] = w; meta[p] = mt;
    }
    __syncthreads();   // hist zeros visible
    for (int p = t; p < NP; p += T) {
        unsigned long long w = keys[p];
        unsigned bin = (unsigned)(w >> 26);
        if ((meta[(unsigned)(w & 0x3FFFu)] >> 16) & 1u) atomicAdd(&hP[bin], 1u);
        else                                            atomicAdd(&hN[bin], 1u);
    }
    __syncthreads();

    // inclusive scan of both 2048-bin histograms (Hillis-Steele, 2 pos/thread)
    for (int off = 1; off < NBIN; off <<= 1) {
        int i0 = t, i1 = t + T;
        unsigned a0 = 0, a1 = 0, b0 = 0, b1 = 0;
        if (i0 >= off) { a0 = hP[i0 - off]; b0 = hN[i0 - off]; }
        if (i1 >= off) { a1 = hP[i1 - off]; b1 = hN[i1 - off]; }
        __syncthreads();
        hP[i0] += a0; hN[i0] += b0;
        hP[i1] += a1; hN[i1] += b1;
        __syncthreads();
    }

    const unsigned total_pos = hP[NBIN - 1];
    const unsigned n_pos = (total_pos < (unsigned)NFG) ? total_pos : (unsigned)NFG;
    const unsigned quota = (unsigned)NSAMP - n_pos;

    // find boundary bins: first bin where cumulative count reaches the rank
    {
        int i0 = t, i1 = t + T;
        if (total_pos > (unsigned)NFG) {
            unsigned c0 = hP[i0], p0 = i0 ? hP[i0 - 1] : 0u;
            unsigned c1 = hP[i1], p1 = hP[i1 - 1];
            if (c0 >= (unsigned)NFG && p0 < (unsigned)NFG) { sh_bp = (unsigned)i0; sh_befP = p0; }
            if (c1 >= (unsigned)NFG && p1 < (unsigned)NFG) { sh_bp = (unsigned)i1; sh_befP = p1; }
        }
        unsigned c0 = hN[i0], p0 = i0 ? hN[i0 - 1] : 0u;
        unsigned c1 = hN[i1], p1 = hN[i1 - 1];
        if (c0 >= quota && p0 < quota) { sh_bn = (unsigned)i0; sh_befN = p0; }
        if (c1 >= quota && p1 < quota) { sh_bn = (unsigned)i1; sh_befN = p1; }
    }
    __syncthreads();

    // collect boundary-bin items (expected ~4 each)
    const bool needPsel = (total_pos > (unsigned)NFG);
    {
        unsigned bp = needPsel ? sh_bp : 0xFFFFFFFFu;
        unsigned bn = sh_bn;
        for (int p = t; p < NP; p += T) {
            unsigned long long w = keys[p];
            unsigned bin = (unsigned)(w >> 26);
            bool pos = (meta[(unsigned)(w & 0x3FFFu)] >> 16) & 1u;
            if (pos) {
                if (bin == bp) { unsigned j = atomicAdd(&cntP, 1u); if (j < CAP) LP[j] = w; }
            } else {
                if (bin == bn) { unsigned j = atomicAdd(&cntN, 1u); if (j < CAP) LN[j] = w; }
            }
        }
    }
    __syncthreads();

    // exact rank within boundary bins -> cutoff keys (keys are unique)
    {
        unsigned cp = cntP < CAP ? cntP : CAP;
        unsigned cn = cntN < CAP ? cntN : CAP;
        if (needPsel && (unsigned)t < cp) {
            unsigned long long k = LP[t]; unsigned r = 0;
            for (unsigned l = 0; l < cp; ++l) r += (LP[l] < k);
            if (r == ((unsigned)NFG - sh_befP) - 1u) sh_KP = k;
        }
        if ((unsigned)t < cn) {
            unsigned long long k = LN[t]; unsigned r = 0;
            for (unsigned l = 0; l < cn; ++l) r += (LN[l] < k);
            if (r == (quota - sh_befN) - 1u) sh_KN = k;
        }
    }
    __syncthreads();

    // final selection: exactly 512 items; re-key by RNE-rounded score mantissa.
    // score = 2.0f + r rounds r's 23-bit mantissa m to 2^-22 grid:
    //   h = (m>>1) + ((m&1) & ((m>>1)&1)); ties broken by idx asc.
    {
        unsigned long long KP = sh_KP, KN = sh_KN;
        for (int p = t; p < NP; p += T) {
            unsigned long long w = keys[p];
            unsigned i = (unsigned)(w & 0x3FFFu);
            bool pos = (meta[i] >> 16) & 1u;
            bool sel = pos ? (w <= KP) : (w <= KN);
            if (sel) {
                unsigned mm = 0x7FFFFFu - (unsigned)((w >> 14) & 0x7FFFFFu);
                unsigned h  = (mm >> 1) + ((mm & 1u) & ((mm >> 1) & 1u));
                unsigned j  = atomicAdd(&cntS, 1u);
                selk[j] = (((unsigned long long)(0x7FFFFFu - h)) << 14) | i;
            }
        }
    }
    __syncthreads();

    // bitonic sort the 512 selected keys (ascending == score desc, idx asc)
    for (unsigned k = 2; k <= (unsigned)NSAMP; k <<= 1) {
        for (unsigned j = k >> 1; j > 0; j >>= 1) {
            if (t < NSAMP) {
                unsigned p = (unsigned)t, q = p ^ j;
                if (q > p) {
                    unsigned long long a = selk[p], c = selk[q];
                    bool up = ((p & k) == 0);
                    if ((a > c) == up) { selk[p] = c; selk[q] = a; }
                }
            }
            __syncthreads();
        }
    }

    // gather outputs
    if (t < NSAMP) {
        unsigned i = (unsigned)(selk[t] & 0x3FFFu);
        write_record(boxes, gt_boxes, gt_classes, meta, out, b, i, (unsigned)t);
    }
}

extern "C" void kernel_launch(void* const* d_in, const int* in_sizes, int n_in,
                              void* d_out, int out_size) {
    (void)out_size;
    const float* boxes      = (const float*)d_in[0];
    const float* gt_boxes   = (const float*)d_in[1];
    const int*   gt_classes = (const int*)d_in[2];
    for (int k = 0; k < n_in; ++k) {
        if (in_sizes[k] == BB * NBOX * 4) boxes      = (const float*)d_in[k];
        else if (in_sizes[k] == BB * MGT * 4) gt_boxes = (const float*)d_in[k];
        else if (in_sizes[k] == BB * MGT)     gt_classes = (const int*)d_in[k];
    }
    float* out = (float*)d_out;

    dim3 g1(17, BB);
    roi_match_kernel<<<g1, 256>>>(boxes, gt_boxes);

    size_t smem = (size_t)NP * 8 + 2 * (size_t)CAP * 8 + (size_t)NSAMP * 8
                + (size_t)NP * 4 + 2 * (size_t)NBIN * 4;   // ~130 KB
    cudaFuncSetAttribute(roi_sample_kernel,
                         cudaFuncAttributeMaxDynamicSharedMemorySize, (int)smem);
    roi_sample_kernel<<<BB, 1024, smem>>>(boxes, gt_boxes, gt_classes, out);
}

// round 7
// speedup vs baseline: 1.5149x; 1.0842x over previous
#include <cuda_runtime.h>
#include <stdint.h>

#define BB    32
#define NBOX  8192
#define MGT   256
#define NP    8448        // NBOX + MGT
#define NSAMP 512
#define NFG   128
#define KBIN  256
#define KCAP  4096
#define LCAP  256
#define THRESH (1u << 21)            // keep negatives with inv_m < 2^21 (r > 0.75)
#define MASK37 ((1ull << 37) - 1)

// scratch (device globals -- no allocation allowed)
__device__ unsigned long long g_sel[BB * KCAP];
__device__ unsigned int       g_cnt[BB];

__device__ __forceinline__ uint32_t rotl32(uint32_t x, int d) {
    return (x << d) | (x >> (32 - d));
}

// JAX *partitionable* threefry, key = (0, 42). bits(p) = x0 ^ x1 of
// threefry2x32((0,42), (0, p))
__device__ __forceinline__ uint32_t threefry_bits(uint32_t p) {
    const uint32_t ks0 = 0u, ks1 = 42u, ks2 = 0x1BD11BF0u;  // 0x1BD11BDA ^ 0 ^ 42
    uint32_t x0 = 0u + ks0;
    uint32_t x1 = p + ks1;
#define TF_R(r) { x0 += x1; x1 = rotl32(x1, (r)); x1 ^= x0; }
    TF_R(13) TF_R(15) TF_R(26) TF_R(6)   x0 += ks1; x1 += ks2 + 1u;
    TF_R(17) TF_R(29) TF_R(16) TF_R(24)  x0 += ks2; x1 += ks0 + 2u;
    TF_R(13) TF_R(15) TF_R(26) TF_R(6)   x0 += ks0; x1 += ks1 + 3u;
    TF_R(17) TF_R(29) TF_R(16) TF_R(24)  x0 += ks1; x1 += ks2 + 4u;
    TF_R(13) TF_R(15) TF_R(26) TF_R(6)   x0 += ks2; x1 += ks0 + 5u;
#undef TF_R
    return x0 ^ x1;
}

__global__ void zero_cnt_kernel() {
    if (threadIdx.x < BB) g_cnt[threadIdx.x] = 0u;
}

// packed survivor word: [0:14) idx | [14:37) inv_m | bit37 pos | [38:46) mi
__device__ __forceinline__ void emit(int b, int i, bool pos, int mi) {
    uint32_t m = threefry_bits((uint32_t)(b * NP + i)) >> 9;
    uint32_t invm = 0x7FFFFFu - m;     // asc == r desc
    if (pos || invm < THRESH) {
        unsigned long long w = ((unsigned long long)(unsigned)mi << 38)
            | ((unsigned long long)(pos ? 1u : 0u) << 37)
            | ((unsigned long long)invm << 14) | (unsigned)i;
        unsigned j = atomicAdd(&g_cnt[b], 1u);
        if (j < KCAP) g_sel[b * KCAP + j] = w;
    }
}

// ---------------------------------------------------------------------------
// Kernel 1: max-IoU matching, 2 boxes/thread, valid-gt prefix, if-guarded
// update; emits only prefiltered survivors (compacted).
// grid (17, 32): blocks 0..15 handle 512 proposals each; block 16 the 256 gts.
// ---------------------------------------------------------------------------
__global__ __launch_bounds__(256)
void roi_match_kernel(const float* __restrict__ boxes,
                      const float* __restrict__ gt_boxes) {
    __shared__ float4 sg[MGT];
    __shared__ float  sga[MGT];

    const int b = blockIdx.y;
    const int t = threadIdx.x;
    int nv;
    {
        float4 g = ((const float4*)gt_boxes)[b * MGT + t];
        float mx = fmaxf(fmaxf(g.x, g.y), fmaxf(g.z, g.w));
        bool valid = (mx >= 0.0f);
        sg[t] = g;
        sga[t] = (g.z - g.x) * (g.w - g.y);
        nv = __syncthreads_count(valid);         // valid gts are a prefix
    }

    const bool two = (blockIdx.x < 16);
    const int i0 = two ? (blockIdx.x * 512 + t) : (NBOX + t);
    const int i1 = i0 + 256;

    float4 A = (i0 < NBOX) ? ((const float4*)boxes)[b * NBOX + i0]
                           : ((const float4*)gt_boxes)[b * MGT + (i0 - NBOX)];
    float4 Bx = two ? ((const float4*)boxes)[b * NBOX + i1] : A;

    const float abA = (A.z - A.x) * (A.w - A.y);
    const float abB = (Bx.z - Bx.x) * (Bx.w - Bx.y);

    // running argmax of iou = inter/uni via cross-multiplication.
    // bi=-1 sentinel: first overlapping gt always wins; bi>0 <=> some overlap.
    float biA = -1.0f, buA = 1.0f; int miA = 0;
    float biB = -1.0f, buB = 1.0f; int miB = 0;
#pragma unroll 4
    for (int g = 0; g < nv; ++g) {
        float4 gb = sg[g];
        float ga  = sga[g];
        {
            float dy = fminf(A.z, gb.z) - fmaxf(A.x, gb.x);
            float dx = fminf(A.w, gb.w) - fmaxf(A.y, gb.y);
            if (dy > 0.0f && dx > 0.0f) {
                float inter = dy * dx;
                float uni   = (abA + ga) - inter;
                if (inter * buA > biA * uni) { biA = inter; buA = uni; miA = g; }
            }
        }
        {
            float dy = fminf(Bx.z, gb.z) - fmaxf(Bx.x, gb.x);
            float dx = fminf(Bx.w, gb.w) - fmaxf(Bx.y, gb.y);
            if (dy > 0.0f && dx > 0.0f) {
                float inter = dy * dx;
                float uni   = (abB + ga) - inter;
                if (inter * buB > biB * uni) { biB = inter; buB = uni; miB = g; }
            }
        }
    }
    bool posA = (biA > 0.0f) && (__fdiv_rn(biA, buA) >= 0.5f);
    bool posB = (biB > 0.0f) && (__fdiv_rn(biB, buB) >= 0.5f);

    emit(b, i0, posA, miA);
    if (two) emit(b, i1, posB, miB);
}

// ---------------------------------------------------------------------------
// Kernel 2: per-image select over compacted survivors (~2250) + 512-sort.
// 32 CTAs x 512 threads.
// ---------------------------------------------------------------------------
__global__ __launch_bounds__(512)
void roi_sample_kernel(const float* __restrict__ boxes,
                       const float* __restrict__ gt_boxes,
                       const int*   __restrict__ gt_classes,
                       float* __restrict__ out) {
    extern __shared__ unsigned long long items[];   // KCAP
    __shared__ unsigned hP[KBIN], hN[KBIN], sPc[KBIN], sNc[KBIN];
    __shared__ unsigned wtP[8], wtN[8];
    __shared__ unsigned long long LP[LCAP], LN[LCAP], selk[NSAMP];
    __shared__ unsigned sh_bp, sh_bn, sh_befP, sh_befN;
    __shared__ unsigned cntP, cntN, cntS;
    __shared__ unsigned long long sh_KP, sh_KN;

    const int b = blockIdx.x;
    const int t = threadIdx.x;
    const int T = 512;
    const int lane = t & 31, wid = t >> 5;

    if (t == 0) { cntP = 0; cntN = 0; cntS = 0; sh_KP = MASK37; sh_KN = MASK37; }
    if (t < KBIN) { hP[t] = 0u; hN[t] = 0u; }
    const unsigned M0 = g_cnt[b];
    const unsigned M = (M0 < KCAP) ? M0 : KCAP;
    __syncthreads();

    // load survivors + histogram on inv_m[22:15]  (bits 29..36 of w)
    for (unsigned p = t; p < M; p += T) {
        unsigned long long w = g_sel[b * KCAP + p];
        items[p] = w;
        unsigned bin = (unsigned)(w >> 29) & 0xFFu;
        if ((w >> 37) & 1ull) atomicAdd(&hP[bin], 1u);
        else                  atomicAdd(&hN[bin], 1u);
    }
    __syncthreads();

    // inclusive scan of 256 bins: warp shuffles + tiny cross-warp combine
    unsigned sP = 0, sN = 0;
    if (t < KBIN) {
        sP = hP[t]; sN = hN[t];
#pragma unroll
        for (int off = 1; off < 32; off <<= 1) {
            unsigned vP = __shfl_up_sync(0xFFFFFFFFu, sP, off);
            unsigned vN = __shfl_up_sync(0xFFFFFFFFu, sN, off);
            if (lane >= off) { sP += vP; sN += vN; }
        }
        if (lane == 31) { wtP[wid] = sP; wtN[wid] = sN; }
    }
    __syncthreads();
    if (t < KBIN) {
        unsigned offP = 0, offN = 0;
        for (int ww = 0; ww < wid; ++ww) { offP += wtP[ww]; offN += wtN[ww]; }
        sPc[t] = sP + offP; sNc[t] = sN + offN;
    }
    __syncthreads();

    const unsigned total_pos = sPc[KBIN - 1];
    const unsigned n_pos = (total_pos < (unsigned)NFG) ? total_pos : (unsigned)NFG;
    const unsigned quota = (unsigned)NSAMP - n_pos;
    const bool needPsel = (total_pos > (unsigned)NFG);

    // boundary bins
    if (t < KBIN) {
        unsigned iP = sPc[t], pP = t ? sPc[t - 1] : 0u;
        unsigned iN = sNc[t], pN = t ? sNc[t - 1] : 0u;
        if (needPsel && iP >= (unsigned)NFG && pP < (unsigned)NFG) { sh_bp = (unsigned)t; sh_befP = pP; }
        if (iN >= quota && pN < quota) { sh_bn = (unsigned)t; sh_befN = pN; }
    }
    __syncthreads();

    // collect boundary-bin items (masked 37-bit keys)
    {
        unsigned bp = needPsel ? sh_bp : 0xFFFFFFFFu;
        unsigned bn = sh_bn;
        for (unsigned p = t; p < M; p += T) {
            unsigned long long w = items[p];
            unsigned bin = (unsigned)(w >> 29) & 0xFFu;
            if ((w >> 37) & 1ull) {
                if (bin == bp) { unsigned j = atomicAdd(&cntP, 1u); if (j < LCAP) LP[j] = w & MASK37; }
            } else {
                if (bin == bn) { unsigned j = atomicAdd(&cntN, 1u); if (j < LCAP) LN[j] = w & MASK37; }
            }
        }
    }
    selk[t] = ~0ull;
    __syncthreads();

    // exact rank within boundary bins -> cutoff keys (keys are unique)
    {
        unsigned cp = cntP < LCAP ? cntP : LCAP;
        unsigned cn = cntN < LCAP ? cntN : LCAP;
        if (needPsel && (unsigned)t < cp) {
            unsigned long long k = LP[t]; unsigned r = 0;
            for (unsigned l = 0; l < cp; ++l) r += (LP[l] < k);
            if (r == ((unsigned)NFG - sh_befP) - 1u) sh_KP = k;
        }
        if ((unsigned)t < cn) {
            unsigned long long k = LN[t]; unsigned r = 0;
            for (unsigned l = 0; l < cn; ++l) r += (LN[l] < k);
            if (r == (quota - sh_befN) - 1u) sh_KN = k;
        }
    }
    __syncthreads();

    // final selection (exactly 512); re-key by RNE-rounded score mantissa.
    // score = 2.0f + r rounds r's 23-bit mantissa m to 2^-22 grid:
    //   h = (m>>1) + ((m&1) & ((m>>1)&1)); ties broken by idx asc.
    {
        unsigned long long KP = sh_KP, KN = sh_KN;
        for (unsigned p = t; p < M; p += T) {
            unsigned long long w = items[p];
            unsigned long long kk = w & MASK37;
            bool sel = ((w >> 37) & 1ull) ? (kk <= KP) : (kk <= KN);
            if (sel) {
                unsigned mm = 0x7FFFFFu - (unsigned)((w >> 14) & 0x7FFFFFu);
                unsigned h  = (mm >> 1) + ((mm & 1u) & ((mm >> 1) & 1u));
                unsigned j  = atomicAdd(&cntS, 1u);
                selk[j] = (w & ~(MASK37 ^ 0x3FFFull))           // keep pos|mi (and idx below)
                        & ~0x3FFFull                             // clear idx field first
                        | (((unsigned long long)(0x7FFFFFu - h)) << 14)
                        | (w & 0x3FFFull);
            }
        }
    }
    __syncthreads();

    // bitonic sort 512 keys by low 37 bits asc (== score desc, idx asc);
    // pos/mi ride in the high bits, masked out of comparisons via <<27.
    for (unsigned k = 2; k <= (unsigned)NSAMP; k <<= 1) {
        for (unsigned j = k >> 1; j > 0; j >>= 1) {
            unsigned p = (unsigned)t, q = p ^ j;
            if (q > p) {
                unsigned long long a = selk[p], c = selk[q];
                bool up = ((p & k) == 0);
                if (((a << 27) > (c << 27)) == up) { selk[p] = c; selk[q] = a; }
            }
            __syncthreads();
        }
    }

    // gather outputs
    {
        unsigned long long v = selk[t];
        if ((unsigned)t < cntS) {
            unsigned i  = (unsigned)(v & 0x3FFFu);
            bool pos    = (v >> 37) & 1ull;
            int  mi     = (int)((v >> 38) & 0xFFull);
            float4 roi = (i < NBOX)
                ? ((const float4*)boxes)[b * NBOX + i]
                : ((const float4*)gt_boxes)[b * MGT + (i - NBOX)];
            float4 gb = make_float4(0.f, 0.f, 0.f, 0.f);
            float cls = 0.0f, gidx = -1.0f;
            if (pos) {
                gb   = ((const float4*)gt_boxes)[b * MGT + mi];
                cls  = (float)gt_classes[b * MGT + mi];
                gidx = (float)mi;
            }
            size_t base = (size_t)(b * NSAMP + t);
            float* o1 = out + base * 4;                                   // rois
            o1[0] = roi.x; o1[1] = roi.y; o1[2] = roi.z; o1[3] = roi.w;
            float* o2 = out + (size_t)BB * NSAMP * 4 + base * 4;          // matched gt boxes
            o2[0] = gb.x; o2[1] = gb.y; o2[2] = gb.z; o2[3] = gb.w;
            out[(size_t)2 * BB * NSAMP * 4 + base] = cls;                 // classes
            out[(size_t)2 * BB * NSAMP * 4 + (size_t)BB * NSAMP + base] = gidx; // indices
        }
    }
}

extern "C" void kernel_launch(void* const* d_in, const int* in_sizes, int n_in,
                              void* d_out, int out_size) {
    (void)out_size;
    const float* boxes      = (const float*)d_in[0];
    const float* gt_boxes   = (const float*)d_in[1];
    const int*   gt_classes = (const int*)d_in[2];
    for (int k = 0; k < n_in; ++k) {
        if (in_sizes[k] == BB * NBOX * 4) boxes      = (const float*)d_in[k];
        else if (in_sizes[k] == BB * MGT * 4) gt_boxes = (const float*)d_in[k];
        else if (in_sizes[k] == BB * MGT)     gt_classes = (const int*)d_in[k];
    }
    float* out = (float*)d_out;

    zero_cnt_kernel<<<1, 32>>>();

    dim3 g1(17, BB);
    roi_match_kernel<<<g1, 256>>>(boxes, gt_boxes);

    size_t smem = (size_t)KCAP * 8;   // 32 KB dynamic (items)
    cudaFuncSetAttribute(roi_sample_kernel,
                         cudaFuncAttributeMaxDynamicSharedMemorySize, (int)smem);
    roi_sample_kernel<<<BB, 512, smem>>>(boxes, gt_boxes, gt_classes, out);
}

// round 8
// speedup vs baseline: 1.5300x; 1.0100x over previous
#include <cuda_runtime.h>
#include <stdint.h>

#define BB    32
#define NBOX  8192
#define MGT   256
#define NP    8448        // NBOX + MGT
#define NSAMP 512
#define NFG   128
#define KBIN  256
#define KCAP  4096
#define LCAP  256
#define THRESH (1u << 21)            // keep negatives with inv_m < 2^21 (r > 0.75)
#define MASK37 ((1ull << 37) - 1)

// scratch (device globals -- no allocation allowed; zero-initialized at load,
// and kernel 2 re-zeroes g_cnt after consuming it -> graph-replay safe)
__device__ unsigned long long g_sel[BB * KCAP];
__device__ unsigned int       g_cnt[BB];

__device__ __forceinline__ uint32_t rotl32(uint32_t x, int d) {
    return (x << d) | (x >> (32 - d));
}

// JAX *partitionable* threefry, key = (0, 42). bits(p) = x0 ^ x1 of
// threefry2x32((0,42), (0, p))
__device__ __forceinline__ uint32_t threefry_bits(uint32_t p) {
    const uint32_t ks0 = 0u, ks1 = 42u, ks2 = 0x1BD11BF0u;  // 0x1BD11BDA ^ 0 ^ 42
    uint32_t x0 = 0u + ks0;
    uint32_t x1 = p + ks1;
#define TF_R(r) { x0 += x1; x1 = rotl32(x1, (r)); x1 ^= x0; }
    TF_R(13) TF_R(15) TF_R(26) TF_R(6)   x0 += ks1; x1 += ks2 + 1u;
    TF_R(17) TF_R(29) TF_R(16) TF_R(24)  x0 += ks2; x1 += ks0 + 2u;
    TF_R(13) TF_R(15) TF_R(26) TF_R(6)   x0 += ks0; x1 += ks1 + 3u;
    TF_R(17) TF_R(29) TF_R(16) TF_R(24)  x0 += ks1; x1 += ks2 + 4u;
    TF_R(13) TF_R(15) TF_R(26) TF_R(6)   x0 += ks2; x1 += ks0 + 5u;
#undef TF_R
    return x0 ^ x1;
}

// packed survivor word: [0:14) idx | [14:37) inv_m | bit37 pos | [38:46) mi
__device__ __forceinline__ void emit(int b, int i, bool pos, int mi) {
    uint32_t m = threefry_bits((uint32_t)(b * NP + i)) >> 9;
    uint32_t invm = 0x7FFFFFu - m;     // asc == r desc
    if (pos || invm < THRESH) {
        unsigned long long w = ((unsigned long long)(unsigned)mi << 38)
            | ((unsigned long long)(pos ? 1u : 0u) << 37)
            | ((unsigned long long)invm << 14) | (unsigned)i;
        unsigned j = atomicAdd(&g_cnt[b], 1u);
        if (j < KCAP) g_sel[b * KCAP + j] = w;
    }
}

// ---------------------------------------------------------------------------
// Kernel 1: max-IoU matching, 2 boxes/thread, valid-gt prefix, if-guarded
// update; emits only prefiltered survivors (compacted).
// grid (32, 17): x = image (so consecutive bids mix images -> SM balance),
// y = slice. Slices 0..15 handle 512 proposals; slice 16 the 256 gts.
// ---------------------------------------------------------------------------
__global__ __launch_bounds__(256)
void roi_match_kernel(const float* __restrict__ boxes,
                      const float* __restrict__ gt_boxes) {
    __shared__ float4 sg[MGT];
    __shared__ float  sga[MGT];

    const int b = blockIdx.x;
    const int s = blockIdx.y;
    const int t = threadIdx.x;
    int nv;
    {
        float4 g = ((const float4*)gt_boxes)[b * MGT + t];
        float mx = fmaxf(fmaxf(g.x, g.y), fmaxf(g.z, g.w));
        bool valid = (mx >= 0.0f);
        sg[t] = g;
        sga[t] = (g.z - g.x) * (g.w - g.y);
        nv = __syncthreads_count(valid);         // valid gts are a prefix
    }

    const bool two = (s < 16);
    const int i0 = two ? (s * 512 + t) : (NBOX + t);
    const int i1 = i0 + 256;

    float4 A = (i0 < NBOX) ? ((const float4*)boxes)[b * NBOX + i0]
                           : ((const float4*)gt_boxes)[b * MGT + (i0 - NBOX)];
    float4 Bx = two ? ((const float4*)boxes)[b * NBOX + i1] : A;

    const float abA = (A.z - A.x) * (A.w - A.y);
    const float abB = (Bx.z - Bx.x) * (Bx.w - Bx.y);

    // running argmax of iou = inter/uni via cross-multiplication.
    // bi=-1 sentinel: first overlapping gt always wins; bi>0 <=> some overlap.
    float biA = -1.0f, buA = 1.0f; int miA = 0;
    float biB = -1.0f, buB = 1.0f; int miB = 0;
#pragma unroll 4
    for (int g = 0; g < nv; ++g) {
        float4 gb = sg[g];
        float ga  = sga[g];
        {
            float dy = fminf(A.z, gb.z) - fmaxf(A.x, gb.x);
            float dx = fminf(A.w, gb.w) - fmaxf(A.y, gb.y);
            if (dy > 0.0f && dx > 0.0f) {
                float inter = dy * dx;
                float uni   = (abA + ga) - inter;
                if (inter * buA > biA * uni) { biA = inter; buA = uni; miA = g; }
            }
        }
        {
            float dy = fminf(Bx.z, gb.z) - fmaxf(Bx.x, gb.x);
            float dx = fminf(Bx.w, gb.w) - fmaxf(Bx.y, gb.y);
            if (dy > 0.0f && dx > 0.0f) {
                float inter = dy * dx;
                float uni   = (abB + ga) - inter;
                if (inter * buB > biB * uni) { biB = inter; buB = uni; miB = g; }
            }
        }
    }
    bool posA = (biA > 0.0f) && (__fdiv_rn(biA, buA) >= 0.5f);
    bool posB = (biB > 0.0f) && (__fdiv_rn(biB, buB) >= 0.5f);

    emit(b, i0, posA, miA);
    if (two) emit(b, i1, posB, miB);
}

// ---------------------------------------------------------------------------
// Kernel 2: per-image select over compacted survivors (~2250) + 512-sort.
// 32 CTAs x 512 threads. Resets g_cnt[b] for the next graph replay.
// ---------------------------------------------------------------------------
__global__ __launch_bounds__(512)
void roi_sample_kernel(const float* __restrict__ boxes,
                       const float* __restrict__ gt_boxes,
                       const int*   __restrict__ gt_classes,
                       float* __restrict__ out) {
    extern __shared__ unsigned long long items[];   // KCAP
    __shared__ unsigned hP[KBIN], hN[KBIN], sPc[KBIN], sNc[KBIN];
    __shared__ unsigned wtP[8], wtN[8];
    __shared__ unsigned long long LP[LCAP], LN[LCAP], selk[NSAMP];
    __shared__ unsigned sh_bp, sh_bn, sh_befP, sh_befN;
    __shared__ unsigned cntP, cntN, cntS;
    __shared__ unsigned long long sh_KP, sh_KN;

    const int b = blockIdx.x;
    const int t = threadIdx.x;
    const int T = 512;
    const int lane = t & 31, wid = t >> 5;

    if (t == 0) { cntP = 0; cntN = 0; cntS = 0; sh_KP = MASK37; sh_KN = MASK37; }
    if (t < KBIN) { hP[t] = 0u; hN[t] = 0u; }
    const unsigned M0 = g_cnt[b];
    const unsigned M = (M0 < KCAP) ? M0 : KCAP;
    __syncthreads();
    if (t == 0) g_cnt[b] = 0u;   // reset for next replay (all threads read M0 above)

    // load survivors + histogram on inv_m[22:15]  (bits 29..36 of w)
    for (unsigned p = t; p < M; p += T) {
        unsigned long long w = g_sel[b * KCAP + p];
        items[p] = w;
        unsigned bin = (unsigned)(w >> 29) & 0xFFu;
        if ((w >> 37) & 1ull) atomicAdd(&hP[bin], 1u);
        else                  atomicAdd(&hN[bin], 1u);
    }
    __syncthreads();

    // inclusive scan of 256 bins: warp shuffles + tiny cross-warp combine
    unsigned sP = 0, sN = 0;
    if (t < KBIN) {
        sP = hP[t]; sN = hN[t];
#pragma unroll
        for (int off = 1; off < 32; off <<= 1) {
            unsigned vP = __shfl_up_sync(0xFFFFFFFFu, sP, off);
            unsigned vN = __shfl_up_sync(0xFFFFFFFFu, sN, off);
            if (lane >= off) { sP += vP; sN += vN; }
        }
        if (lane == 31) { wtP[wid] = sP; wtN[wid] = sN; }
    }
    __syncthreads();
    if (t < KBIN) {
        unsigned offP = 0, offN = 0;
        for (int ww = 0; ww < wid; ++ww) { offP += wtP[ww]; offN += wtN[ww]; }
        sPc[t] = sP + offP; sNc[t] = sN + offN;
    }
    __syncthreads();

    const unsigned total_pos = sPc[KBIN - 1];
    const unsigned n_pos = (total_pos < (unsigned)NFG) ? total_pos : (unsigned)NFG;
    const unsigned quota = (unsigned)NSAMP - n_pos;
    const bool needPsel = (total_pos > (unsigned)NFG);

    // boundary bins
    if (t < KBIN) {
        unsigned iP = sPc[t], pP = t ? sPc[t - 1] : 0u;
        unsigned iN = sNc[t], pN = t ? sNc[t - 1] : 0u;
        if (needPsel && iP >= (unsigned)NFG && pP < (unsigned)NFG) { sh_bp = (unsigned)t; sh_befP = pP; }
        if (iN >= quota && pN < quota) { sh_bn = (unsigned)t; sh_befN = pN; }
    }
    __syncthreads();

    // collect boundary-bin items (masked 37-bit keys)
    {
        unsigned bp = needPsel ? sh_bp : 0xFFFFFFFFu;
        unsigned bn = sh_bn;
        for (unsigned p = t; p < M; p += T) {
            unsigned long long w = items[p];
            unsigned bin = (unsigned)(w >> 29) & 0xFFu;
            if ((w >> 37) & 1ull) {
                if (bin == bp) { unsigned j = atomicAdd(&cntP, 1u); if (j < LCAP) LP[j] = w & MASK37; }
            } else {
                if (bin == bn) { unsigned j = atomicAdd(&cntN, 1u); if (j < LCAP) LN[j] = w & MASK37; }
            }
        }
    }
    selk[t] = ~0ull;
    __syncthreads();

    // exact rank within boundary bins -> cutoff keys (keys are unique)
    {
        unsigned cp = cntP < LCAP ? cntP : LCAP;
        unsigned cn = cntN < LCAP ? cntN : LCAP;
        if (needPsel && (unsigned)t < cp) {
            unsigned long long k = LP[t]; unsigned r = 0;
            for (unsigned l = 0; l < cp; ++l) r += (LP[l] < k);
            if (r == ((unsigned)NFG - sh_befP) - 1u) sh_KP = k;
        }
        if ((unsigned)t < cn) {
            unsigned long long k = LN[t]; unsigned r = 0;
            for (unsigned l = 0; l < cn; ++l) r += (LN[l] < k);
            if (r == (quota - sh_befN) - 1u) sh_KN = k;
        }
    }
    __syncthreads();

    // final selection (exactly 512); re-key by RNE-rounded score mantissa.
    // score = 2.0f + r rounds r's 23-bit mantissa m to 2^-22 grid:
    //   h = (m>>1) + ((m&1) & ((m>>1)&1)); ties broken by idx asc.
    {
        unsigned long long KP = sh_KP, KN = sh_KN;
        for (unsigned p = t; p < M; p += T) {
            unsigned long long w = items[p];
            unsigned long long kk = w & MASK37;
            bool sel = ((w >> 37) & 1ull) ? (kk <= KP) : (kk <= KN);
            if (sel) {
                unsigned mm = 0x7FFFFFu - (unsigned)((w >> 14) & 0x7FFFFFu);
                unsigned h  = (mm >> 1) + ((mm & 1u) & ((mm >> 1) & 1u));
                unsigned j  = atomicAdd(&cntS, 1u);
                selk[j] = (w & ~MASK37)                        // keep pos|mi high bits
                        | (((unsigned long long)(0x7FFFFFu - h)) << 14)
                        | (w & 0x3FFFull);
            }
        }
    }
    __syncthreads();

    // bitonic sort 512 keys by low 37 bits asc (== score desc, idx asc);
    // pos/mi ride in the high bits, masked out of comparisons via <<27.
    for (unsigned k = 2; k <= (unsigned)NSAMP; k <<= 1) {
        for (unsigned j = k >> 1; j > 0; j >>= 1) {
            unsigned p = (unsigned)t, q = p ^ j;
            if (q > p) {
                unsigned long long a = selk[p], c = selk[q];
                bool up = ((p & k) == 0);
                if (((a << 27) > (c << 27)) == up) { selk[p] = c; selk[q] = a; }
            }
            __syncthreads();
        }
    }

    // gather outputs
    {
        unsigned long long v = selk[t];
        if ((unsigned)t < cntS) {
            unsigned i  = (unsigned)(v & 0x3FFFu);
            bool pos    = (v >> 37) & 1ull;
            int  mi     = (int)((v >> 38) & 0xFFull);
            float4 roi = (i < NBOX)
                ? ((const float4*)boxes)[b * NBOX + i]
                : ((const float4*)gt_boxes)[b * MGT + (i - NBOX)];
            float4 gb = make_float4(0.f, 0.f, 0.f, 0.f);
            float cls = 0.0f, gidx = -1.0f;
            if (pos) {
                gb   = ((const float4*)gt_boxes)[b * MGT + mi];
                cls  = (float)gt_classes[b * MGT + mi];
                gidx = (float)mi;
            }
            size_t base = (size_t)(b * NSAMP + t);
            float* o1 = out + base * 4;                                   // rois
            o1[0] = roi.x; o1[1] = roi.y; o1[2] = roi.z; o1[3] = roi.w;
            float* o2 = out + (size_t)BB * NSAMP * 4 + base * 4;          // matched gt boxes
            o2[0] = gb.x; o2[1] = gb.y; o2[2] = gb.z; o2[3] = gb.w;
            out[(size_t)2 * BB * NSAMP * 4 + base] = cls;                 // classes
            out[(size_t)2 * BB * NSAMP * 4 + (size_t)BB * NSAMP + base] = gidx; // indices
        }
    }
}

extern "C" void kernel_launch(void* const* d_in, const int* in_sizes, int n_in,
                              void* d_out, int out_size) {
    (void)out_size;
    const float* boxes      = (const float*)d_in[0];
    const float* gt_boxes   = (const float*)d_in[1];
    const int*   gt_classes = (const int*)d_in[2];
    for (int k = 0; k < n_in; ++k) {
        if (in_sizes[k] == BB * NBOX * 4) boxes      = (const float*)d_in[k];
        else if (in_sizes[k] == BB * MGT * 4) gt_boxes = (const float*)d_in[k];
        else if (in_sizes[k] == BB * MGT)     gt_classes = (const int*)d_in[k];
    }
    float* out = (float*)d_out;

    dim3 g1(BB, 17);   // x = image -> consecutive bids mix images across SMs
    roi_match_kernel<<<g1, 256>>>(boxes, gt_boxes);

    size_t smem = (size_t)KCAP * 8;   // 32 KB dynamic (items)
    cudaFuncSetAttribute(roi_sample_kernel,
                         cudaFuncAttributeMaxDynamicSharedMemorySize, (int)smem);
    roi_sample_kernel<<<BB, 512, smem>>>(boxes, gt_boxes, gt_classes, out);
}